// round 4
// baseline (speedup 1.0000x reference)
#include <cuda_runtime.h>
#include <cuda_bf16.h>

// Problem constants (fixed by the reference).
#define N_NODES 50000
#define N_EDGES 600000
#define DIM 128
#define LN_EPS 1e-5f

// ---------------- scratch (static device globals; no allocation) -------------
__device__ float4 g_agg4[N_NODES * (DIM / 4)];   // 25.6 MB aggregation buffer
__device__ float  g_deg_out[N_NODES];
__device__ float  g_deg_in[N_NODES];
__device__ float  g_norm_out[N_NODES];
__device__ float  g_norm_in[N_NODES];

// ---------------- f32x2 packed-FMA helpers (Blackwell) -----------------------
__device__ __forceinline__ unsigned long long pack2(float x) {
    unsigned long long r;
    asm("mov.b64 %0, {%1, %1};" : "=l"(r) : "f"(x));
    return r;
}
__device__ __forceinline__ void unpack2(unsigned long long v, float& a, float& b) {
    asm("mov.b64 {%0, %1}, %2;" : "=f"(a), "=f"(b) : "l"(v));
}
__device__ __forceinline__ void fma2(unsigned long long& d, unsigned long long a,
                                     unsigned long long b) {
    // d = a * b + d  (elementwise on packed f32x2)
    asm("fma.rn.f32x2 %0, %1, %2, %0;" : "+l"(d) : "l"(a), "l"(b));
}

// ---------------- K0: zero agg + degree counters ------------------------------
__global__ void zero_kernel(int nN) {
    int i = blockIdx.x * blockDim.x + threadIdx.x;
    int tot = nN * (DIM / 4);
    if (i < tot) g_agg4[i] = make_float4(0.f, 0.f, 0.f, 0.f);
    if (i < nN) { g_deg_out[i] = 0.f; g_deg_in[i] = 0.f; }
}

// ---------------- K1: degrees --------------------------------------------------
__global__ void degree_kernel(const int* __restrict__ src,
                              const int* __restrict__ dst, int nE) {
    int i = blockIdx.x * blockDim.x + threadIdx.x;
    if (i < nE) {
        atomicAdd(&g_deg_out[src[i]], 1.f);
        atomicAdd(&g_deg_in[dst[i]], 1.f);
    }
}

// ---------------- K2: norms ----------------------------------------------------
__global__ void norm_kernel(int nN) {
    int i = blockIdx.x * blockDim.x + threadIdx.x;
    if (i < nN) {
        g_norm_out[i] = rsqrtf(fmaxf(g_deg_out[i], 1.f));
        g_norm_in[i]  = rsqrtf(fmaxf(g_deg_in[i], 1.f));
    }
}

// ---------------- K3: edge scatter (warp per edge, float4 atomics) ------------
__global__ void scatter_kernel(const float* __restrict__ feat,
                               const int* __restrict__ src,
                               const int* __restrict__ dst, int nE) {
    int gtid = blockIdx.x * blockDim.x + threadIdx.x;
    int e = gtid >> 5;
    int lane = gtid & 31;
    if (e >= nE) return;
    int s = __ldg(src + e);
    int d = __ldg(dst + e);
    float ns = __ldg(&g_norm_out[s]);
    float4 v = __ldg(reinterpret_cast<const float4*>(feat) + (size_t)s * 32 + lane);
    v.x *= ns; v.y *= ns; v.z *= ns; v.w *= ns;
    atomicAdd(&g_agg4[(size_t)d * 32 + lane], v);   // sm_90+ vector reduction
}

// ---------------- K4: fused GEMM (256x128 W in smem) + bias/scale + LN + ReLU --
// y = in_norm*(agg@fc_w) + in_norm*fc_b + feat@res_w ; LN(y)*g+b ; relu
// One warp processes 4 nodes; lane owns output columns [4*lane, 4*lane+4).
__global__ void __launch_bounds__(512, 1)
final_kernel(const float* __restrict__ feat,
             const float* __restrict__ fc_w, const float* __restrict__ fc_b,
             const float* __restrict__ res_w,
             const float* __restrict__ ln_g, const float* __restrict__ ln_b,
             float* __restrict__ out, int nN) {
    extern __shared__ float ws[];                       // [256][128] fp32 = 128 KB
    float4* ws4 = reinterpret_cast<float4*>(ws);
    const float4* fw4 = reinterpret_cast<const float4*>(fc_w);
    const float4* rw4 = reinterpret_cast<const float4*>(res_w);
    int tid = threadIdx.x;
#pragma unroll
    for (int i = tid; i < 4096; i += 512) {
        ws4[i] = fw4[i];            // rows 0..127  : fc_w
        ws4[4096 + i] = rw4[i];     // rows 128..255: res_w
    }
    __syncthreads();

    int lane = tid & 31;
    int wg = blockIdx.x * 16 + (tid >> 5);
    int v0 = wg * 4;
    if (v0 >= nN) return;

    const float* ga = reinterpret_cast<const float*>(g_agg4);

    // load x = [in_norm*agg_row(128) ; feat_row(128)], distributed 8 vals/lane/node
    float xr[4][8];
    float inrm[4];
#pragma unroll
    for (int n = 0; n < 4; n++) {
        int v = min(v0 + n, nN - 1);
        float t = __ldg(&g_norm_in[v]);
        inrm[n] = t;
        size_t base = (size_t)v * DIM + lane;
#pragma unroll
        for (int j = 0; j < 4; j++) {
            xr[n][j]     = t * __ldg(ga + base + 32 * j);
            xr[n][4 + j] = __ldg(feat + base + 32 * j);
        }
    }

    unsigned long long acc[4][2];
#pragma unroll
    for (int n = 0; n < 4; n++) { acc[n][0] = 0ull; acc[n][1] = 0ull; }

    const ulonglong2* wsU = reinterpret_cast<const ulonglong2*>(ws);

#pragma unroll
    for (int j = 0; j < 8; j++) {
        float a0 = xr[0][j], a1 = xr[1][j], a2 = xr[2][j], a3 = xr[3][j];
        int kbase = j * 32;
#pragma unroll 4
        for (int l = 0; l < 32; l++) {
            ulonglong2 w = wsU[(kbase + l) * 32 + lane];
            unsigned long long x0 = pack2(__shfl_sync(0xffffffffu, a0, l));
            unsigned long long x1 = pack2(__shfl_sync(0xffffffffu, a1, l));
            unsigned long long x2 = pack2(__shfl_sync(0xffffffffu, a2, l));
            unsigned long long x3 = pack2(__shfl_sync(0xffffffffu, a3, l));
            fma2(acc[0][0], x0, w.x); fma2(acc[0][1], x0, w.y);
            fma2(acc[1][0], x1, w.x); fma2(acc[1][1], x1, w.y);
            fma2(acc[2][0], x2, w.x); fma2(acc[2][1], x2, w.y);
            fma2(acc[3][0], x3, w.x); fma2(acc[3][1], x3, w.y);
        }
    }

    // epilogue: bias (scaled by in_norm), two-pass LayerNorm, ReLU, store
    float4 b4  = __ldg(reinterpret_cast<const float4*>(fc_b) + lane);
    float4 g4  = __ldg(reinterpret_cast<const float4*>(ln_g) + lane);
    float4 bb4 = __ldg(reinterpret_cast<const float4*>(ln_b) + lane);

#pragma unroll
    for (int n = 0; n < 4; n++) {
        float y0, y1, y2, y3;
        unpack2(acc[n][0], y0, y1);
        unpack2(acc[n][1], y2, y3);
        float t = inrm[n];
        y0 = fmaf(t, b4.x, y0);
        y1 = fmaf(t, b4.y, y1);
        y2 = fmaf(t, b4.z, y2);
        y3 = fmaf(t, b4.w, y3);

        float s = y0 + y1 + y2 + y3;
#pragma unroll
        for (int o = 16; o > 0; o >>= 1) s += __shfl_xor_sync(0xffffffffu, s, o);
        float mu = s * (1.0f / 128.0f);

        float d0 = y0 - mu, d1 = y1 - mu, d2 = y2 - mu, d3 = y3 - mu;
        float ss = d0 * d0 + d1 * d1 + d2 * d2 + d3 * d3;
#pragma unroll
        for (int o = 16; o > 0; o >>= 1) ss += __shfl_xor_sync(0xffffffffu, ss, o);
        float rs = rsqrtf(ss * (1.0f / 128.0f) + LN_EPS);

        float4 o4;
        o4.x = fmaxf(fmaf(d0 * rs, g4.x, bb4.x), 0.f);
        o4.y = fmaxf(fmaf(d1 * rs, g4.y, bb4.y), 0.f);
        o4.z = fmaxf(fmaf(d2 * rs, g4.z, bb4.z), 0.f);
        o4.w = fmaxf(fmaf(d3 * rs, g4.w, bb4.w), 0.f);

        int v = v0 + n;
        if (v < nN)
            reinterpret_cast<float4*>(out)[(size_t)v * 32 + lane] = o4;
    }
}

// ---------------- launcher -----------------------------------------------------
extern "C" void kernel_launch(void* const* d_in, const int* in_sizes, int n_in,
                              void* d_out, int out_size) {
    const float* feat  = (const float*)d_in[0];
    const int*   src   = (const int*)d_in[1];
    const int*   dst   = (const int*)d_in[2];
    const float* fc_w  = (const float*)d_in[3];
    const float* fc_b  = (const float*)d_in[4];
    const float* res_w = (const float*)d_in[5];
    const float* ln_g  = (const float*)d_in[6];
    const float* ln_b  = (const float*)d_in[7];
    float* out = (float*)d_out;

    int nN = in_sizes[0] / DIM;   // 50000
    int nE = in_sizes[1];         // 600000

    // K0: zero agg + degree counters
    {
        int tot = nN * (DIM / 4);
        zero_kernel<<<(tot + 255) / 256, 256>>>(nN);
    }
    // K1: degrees
    degree_kernel<<<(nE + 255) / 256, 256>>>(src, dst, nE);
    // K2: norms
    norm_kernel<<<(nN + 255) / 256, 256>>>(nN);
    // K3: scatter-add of normalized source features (warp per edge)
    {
        long long threads = (long long)nE * 32;
        int blocks = (int)((threads + 255) / 256);
        scatter_kernel<<<blocks, 256>>>(feat, src, dst, nE);
    }
    // K4: fused GEMM + bias + in_norm scale + residual GEMM + LN + ReLU
    {
        const int SMEM = 256 * 128 * 4;  // 128 KB
        cudaFuncSetAttribute(final_kernel,
                             cudaFuncAttributeMaxDynamicSharedMemorySize, SMEM);
        int blocks = (nN + 63) / 64;     // 64 nodes per block (16 warps x 4)
        final_kernel<<<blocks, 512, SMEM>>>(feat, fc_w, fc_b, res_w, ln_g, ln_b,
                                            out, nN);
    }
}

// round 5
// speedup vs baseline: 1.1975x; 1.1975x over previous
#include <cuda_runtime.h>
#include <cuda_bf16.h>

#define N_NODES 50000
#define N_EDGES 600000
#define DIM 128
#define LN_EPS 1e-5f

// ---------------- scratch (static device globals; no allocation) -------------
__device__ float4 g_agg4[N_NODES * (DIM / 4)];   // 25.6 MB aggregation buffer
__device__ float  g_deg_out[N_NODES];
__device__ float  g_deg_in[N_NODES];

// ---------------- f32x2 packed-FMA helpers (Blackwell) -----------------------
__device__ __forceinline__ unsigned long long pack2(float x) {
    unsigned long long r;
    asm("mov.b64 %0, {%1, %1};" : "=l"(r) : "f"(x));
    return r;
}
__device__ __forceinline__ void unpack2(unsigned long long v, float& a, float& b) {
    asm("mov.b64 {%0, %1}, %2;" : "=f"(a), "=f"(b) : "l"(v));
}
__device__ __forceinline__ void fma2(unsigned long long& d, unsigned long long a,
                                     unsigned long long b) {
    asm("fma.rn.f32x2 %0, %1, %2, %0;" : "+l"(d) : "l"(a), "l"(b));
}

// ---------------- K0: zero agg + degree counters ------------------------------
__global__ void zero_kernel(int nN) {
    int i = blockIdx.x * blockDim.x + threadIdx.x;
    int tot = nN * (DIM / 4);
    if (i < tot) g_agg4[i] = make_float4(0.f, 0.f, 0.f, 0.f);
    if (i < nN) { g_deg_out[i] = 0.f; g_deg_in[i] = 0.f; }
}

// ---------------- K1: degrees --------------------------------------------------
__global__ void degree_kernel(const int* __restrict__ src,
                              const int* __restrict__ dst, int nE) {
    int i = blockIdx.x * blockDim.x + threadIdx.x;
    if (i < nE) {
        atomicAdd(&g_deg_out[src[i]], 1.f);
        atomicAdd(&g_deg_in[dst[i]], 1.f);
    }
}

// ---------------- K2: edge scatter (warp per 2 edges, float4 atomics) ---------
// norm_out computed inline (saves a kernel + array); __ldcg bypasses L1 for the
// 25.6MB random gather working set; 2 independent edges per warp for MLP.
__global__ void __launch_bounds__(256)
scatter_kernel(const float* __restrict__ feat,
               const int* __restrict__ src,
               const int* __restrict__ dst, int nE) {
    int gtid = blockIdx.x * blockDim.x + threadIdx.x;
    int w = gtid >> 5;
    int lane = gtid & 31;
    int e0 = w * 2;
    if (e0 >= nE) return;
    int e1 = e0 + 1;
    bool has1 = (e1 < nE);

    int s0 = __ldg(src + e0);
    int d0 = __ldg(dst + e0);
    int s1 = has1 ? __ldg(src + e1) : s0;
    int d1 = has1 ? __ldg(dst + e1) : d0;

    float ns0 = rsqrtf(fmaxf(__ldg(&g_deg_out[s0]), 1.f));
    float ns1 = rsqrtf(fmaxf(__ldg(&g_deg_out[s1]), 1.f));

    const float4* f4 = reinterpret_cast<const float4*>(feat);
    float4 v0 = __ldcg(f4 + (size_t)s0 * 32 + lane);
    float4 v1 = __ldcg(f4 + (size_t)s1 * 32 + lane);

    v0.x *= ns0; v0.y *= ns0; v0.z *= ns0; v0.w *= ns0;
    atomicAdd(&g_agg4[(size_t)d0 * 32 + lane], v0);
    if (has1) {
        v1.x *= ns1; v1.y *= ns1; v1.z *= ns1; v1.w *= ns1;
        atomicAdd(&g_agg4[(size_t)d1 * 32 + lane], v1);
    }
}

// ---------------- K3: fused GEMM + bias/scale + LN + ReLU ---------------------
// 256 threads, 8 warps x 8 nodes = 64 nodes/block.
// smem: W [256x128] fp32 (128KB) + x staging [64x256] fp32 (64KB) = 192KB.
// Lane owns output columns [4*lane, 4*lane+4). x broadcast via LDS.128 (no shfl).
__global__ void __launch_bounds__(256, 1)
final_kernel(const float* __restrict__ feat,
             const float* __restrict__ fc_w, const float* __restrict__ fc_b,
             const float* __restrict__ res_w,
             const float* __restrict__ ln_g, const float* __restrict__ ln_b,
             float* __restrict__ out, int nN) {
    extern __shared__ float smem_f[];
    float* ws = smem_f;              // 32768 floats
    float* xs = smem_f + 32768;      // 16384 floats

    int tid = threadIdx.x;
    {
        float4* ws4 = reinterpret_cast<float4*>(ws);
        const float4* fw4 = reinterpret_cast<const float4*>(fc_w);
        const float4* rw4 = reinterpret_cast<const float4*>(res_w);
#pragma unroll
        for (int i = tid; i < 4096; i += 256) {
            ws4[i]        = fw4[i];   // K rows 0..127  : fc_w
            ws4[4096 + i] = rw4[i];   // K rows 128..255: res_w
        }
    }
    __syncthreads();

    int lane = tid & 31;
    int warp = tid >> 5;
    int v0 = blockIdx.x * 64 + warp * 8;
    if (v0 >= nN) return;

    const float* ga = reinterpret_cast<const float*>(g_agg4);
    float* xw = xs + warp * 8 * 256;   // this warp's 8 node rows

    float inrm[8];
#pragma unroll
    for (int n = 0; n < 8; n++) {
        int v = min(v0 + n, nN - 1);
        float t = rsqrtf(fmaxf(__ldg(&g_deg_in[v]), 1.f));
        inrm[n] = t;
        size_t base = (size_t)v * DIM + lane;
        float* row = xw + n * 256;
#pragma unroll
        for (int j = 0; j < 4; j++) {
            row[lane + 32 * j]       = t * __ldg(ga + base + 32 * j);
            row[128 + lane + 32 * j] = __ldg(feat + base + 32 * j);
        }
    }
    __syncwarp();

    unsigned long long acc[8][2];
#pragma unroll
    for (int n = 0; n < 8; n++) { acc[n][0] = 0ull; acc[n][1] = 0ull; }

    const ulonglong2* wsU = reinterpret_cast<const ulonglong2*>(ws);

#pragma unroll 2
    for (int k4 = 0; k4 < 64; k4++) {
        float xf[8][4];
#pragma unroll
        for (int n = 0; n < 8; n++) {
            float4 q = reinterpret_cast<const float4*>(xw + n * 256)[k4]; // broadcast
            xf[n][0] = q.x; xf[n][1] = q.y; xf[n][2] = q.z; xf[n][3] = q.w;
        }
#pragma unroll
        for (int kk = 0; kk < 4; kk++) {
            ulonglong2 w = wsU[(k4 * 4 + kk) * 32 + lane];
#pragma unroll
            for (int n = 0; n < 8; n++) {
                unsigned long long p = pack2(xf[n][kk]);
                fma2(acc[n][0], p, w.x);
                fma2(acc[n][1], p, w.y);
            }
        }
    }

    float4 b4  = __ldg(reinterpret_cast<const float4*>(fc_b) + lane);
    float4 g4  = __ldg(reinterpret_cast<const float4*>(ln_g) + lane);
    float4 bb4 = __ldg(reinterpret_cast<const float4*>(ln_b) + lane);

#pragma unroll
    for (int n = 0; n < 8; n++) {
        float y0, y1, y2, y3;
        unpack2(acc[n][0], y0, y1);
        unpack2(acc[n][1], y2, y3);
        float t = inrm[n];
        y0 = fmaf(t, b4.x, y0);
        y1 = fmaf(t, b4.y, y1);
        y2 = fmaf(t, b4.z, y2);
        y3 = fmaf(t, b4.w, y3);

        float s = y0 + y1 + y2 + y3;
#pragma unroll
        for (int o = 16; o > 0; o >>= 1) s += __shfl_xor_sync(0xffffffffu, s, o);
        float mu = s * (1.0f / 128.0f);

        float d0 = y0 - mu, d1 = y1 - mu, d2 = y2 - mu, d3 = y3 - mu;
        float ss = d0 * d0 + d1 * d1 + d2 * d2 + d3 * d3;
#pragma unroll
        for (int o = 16; o > 0; o >>= 1) ss += __shfl_xor_sync(0xffffffffu, ss, o);
        float rs = rsqrtf(ss * (1.0f / 128.0f) + LN_EPS);

        float4 o4;
        o4.x = fmaxf(fmaf(d0 * rs, g4.x, bb4.x), 0.f);
        o4.y = fmaxf(fmaf(d1 * rs, g4.y, bb4.y), 0.f);
        o4.z = fmaxf(fmaf(d2 * rs, g4.z, bb4.z), 0.f);
        o4.w = fmaxf(fmaf(d3 * rs, g4.w, bb4.w), 0.f);

        int v = v0 + n;
        if (v < nN)
            reinterpret_cast<float4*>(out)[(size_t)v * 32 + lane] = o4;
    }
}

// ---------------- launcher -----------------------------------------------------
extern "C" void kernel_launch(void* const* d_in, const int* in_sizes, int n_in,
                              void* d_out, int out_size) {
    const float* feat  = (const float*)d_in[0];
    const int*   src   = (const int*)d_in[1];
    const int*   dst   = (const int*)d_in[2];
    const float* fc_w  = (const float*)d_in[3];
    const float* fc_b  = (const float*)d_in[4];
    const float* res_w = (const float*)d_in[5];
    const float* ln_g  = (const float*)d_in[6];
    const float* ln_b  = (const float*)d_in[7];
    float* out = (float*)d_out;

    int nN = in_sizes[0] / DIM;   // 50000
    int nE = in_sizes[1];         // 600000

    // K0: zero agg + degree counters
    {
        int tot = nN * (DIM / 4);
        zero_kernel<<<(tot + 255) / 256, 256>>>(nN);
    }
    // K1: degrees
    degree_kernel<<<(nE + 255) / 256, 256>>>(src, dst, nE);
    // K2: scatter-add of normalized source features (warp per 2 edges)
    {
        long long warps = ((long long)nE + 1) / 2;
        long long threads = warps * 32;
        int blocks = (int)((threads + 255) / 256);
        scatter_kernel<<<blocks, 256>>>(feat, src, dst, nE);
    }
    // K3: fused GEMM + bias + in_norm scale + residual GEMM + LN + ReLU
    {
        const int SMEM = (32768 + 16384) * 4;  // 192 KB
        cudaFuncSetAttribute(final_kernel,
                             cudaFuncAttributeMaxDynamicSharedMemorySize, SMEM);
        int blocks = (nN + 63) / 64;
        final_kernel<<<blocks, 256, SMEM>>>(feat, fc_w, fc_b, res_w, ln_g, ln_b,
                                            out, nN);
    }
}

// round 6
// speedup vs baseline: 1.2940x; 1.0806x over previous
#include <cuda_runtime.h>
#include <cuda_bf16.h>

#define N_NODES 50000
#define N_EDGES 600000
#define DIM 128
#define LN_EPS 1e-5f

// ---------------- scratch (static device globals; no allocation) -------------
__device__ float4 g_agg4[N_NODES * (DIM / 4)];   // 25.6 MB aggregation buffer
__device__ float  g_deg_out[N_NODES];
__device__ float  g_deg_in[N_NODES];

// ---------------- f32x2 packed-FMA helpers (Blackwell) -----------------------
__device__ __forceinline__ unsigned long long pack2(float x) {
    unsigned long long r;
    asm("mov.b64 %0, {%1, %1};" : "=l"(r) : "f"(x));
    return r;
}
__device__ __forceinline__ void unpack2(unsigned long long v, float& a, float& b) {
    asm("mov.b64 {%0, %1}, %2;" : "=f"(a), "=f"(b) : "l"(v));
}
__device__ __forceinline__ void fma2(unsigned long long& d, unsigned long long a,
                                     unsigned long long b) {
    asm("fma.rn.f32x2 %0, %1, %2, %0;" : "+l"(d) : "l"(a), "l"(b));
}

// ---------------- K0: zero agg + degree counters ------------------------------
__global__ void zero_kernel(int nN) {
    int i = blockIdx.x * blockDim.x + threadIdx.x;
    int tot = nN * (DIM / 4);
    if (i < tot) g_agg4[i] = make_float4(0.f, 0.f, 0.f, 0.f);
    if (i < nN) { g_deg_out[i] = 0.f; g_deg_in[i] = 0.f; }
}

// ---------------- K1: degrees --------------------------------------------------
__global__ void degree_kernel(const int* __restrict__ src,
                              const int* __restrict__ dst, int nE) {
    int i = blockIdx.x * blockDim.x + threadIdx.x;
    if (i < nE) {
        atomicAdd(&g_deg_out[src[i]], 1.f);
        atomicAdd(&g_deg_in[dst[i]], 1.f);
    }
}

// ---------------- K2: edge scatter (warp per 2 edges, float4 atomics) ---------
__global__ void __launch_bounds__(256)
scatter_kernel(const float* __restrict__ feat,
               const int* __restrict__ src,
               const int* __restrict__ dst, int nE) {
    int gtid = blockIdx.x * blockDim.x + threadIdx.x;
    int w = gtid >> 5;
    int lane = gtid & 31;
    int e0 = w * 2;
    if (e0 >= nE) return;
    int e1 = e0 + 1;
    bool has1 = (e1 < nE);

    int s0 = __ldg(src + e0);
    int d0 = __ldg(dst + e0);
    int s1 = has1 ? __ldg(src + e1) : s0;
    int d1 = has1 ? __ldg(dst + e1) : d0;

    float ns0 = rsqrtf(fmaxf(__ldg(&g_deg_out[s0]), 1.f));
    float ns1 = rsqrtf(fmaxf(__ldg(&g_deg_out[s1]), 1.f));

    const float4* f4 = reinterpret_cast<const float4*>(feat);
    float4 v0 = __ldcg(f4 + (size_t)s0 * 32 + lane);
    float4 v1 = __ldcg(f4 + (size_t)s1 * 32 + lane);

    v0.x *= ns0; v0.y *= ns0; v0.z *= ns0; v0.w *= ns0;
    atomicAdd(&g_agg4[(size_t)d0 * 32 + lane], v0);
    if (has1) {
        v1.x *= ns1; v1.y *= ns1; v1.z *= ns1; v1.w *= ns1;
        atomicAdd(&g_agg4[(size_t)d1 * 32 + lane], v1);
    }
}

// ---------------- K3: fused GEMM + bias/scale + LN + ReLU ---------------------
// 512 threads = 16 warps x 6 nodes = 96 nodes/block (4 warps/SMSP for latency
// hiding). smem: W [256x128] fp32 (128KB) + x staging [96x256] (96KB) = 224KB.
// Lane owns output columns [4*lane, 4*lane+4). x broadcast via LDS.128.
__global__ void __launch_bounds__(512, 1)
final_kernel(const float* __restrict__ feat,
             const float* __restrict__ fc_w, const float* __restrict__ fc_b,
             const float* __restrict__ res_w,
             const float* __restrict__ ln_g, const float* __restrict__ ln_b,
             float* __restrict__ out, int nN) {
    extern __shared__ float smem_f[];
    float* ws = smem_f;              // 32768 floats (128 KB)
    float* xs = smem_f + 32768;      // 24576 floats (96 KB)

    int tid = threadIdx.x;
    {
        float4* ws4 = reinterpret_cast<float4*>(ws);
        const float4* fw4 = reinterpret_cast<const float4*>(fc_w);
        const float4* rw4 = reinterpret_cast<const float4*>(res_w);
#pragma unroll
        for (int i = tid; i < 4096; i += 512) {
            ws4[i]        = fw4[i];   // K rows 0..127  : fc_w
            ws4[4096 + i] = rw4[i];   // K rows 128..255: res_w
        }
    }
    __syncthreads();

    int lane = tid & 31;
    int warp = tid >> 5;
    int v0 = blockIdx.x * 96 + warp * 6;
    if (v0 >= nN) return;

    const float* ga = reinterpret_cast<const float*>(g_agg4);
    float* xw = xs + warp * 6 * 256;   // this warp's 6 node rows

    float inrm[6];
#pragma unroll
    for (int n = 0; n < 6; n++) {
        int v = min(v0 + n, nN - 1);
        float t = rsqrtf(fmaxf(__ldg(&g_deg_in[v]), 1.f));
        inrm[n] = t;
        size_t base = (size_t)v * DIM + lane;
        float* row = xw + n * 256;
#pragma unroll
        for (int j = 0; j < 4; j++) {
            row[lane + 32 * j]       = t * __ldg(ga + base + 32 * j);
            row[128 + lane + 32 * j] = __ldg(feat + base + 32 * j);
        }
    }
    __syncwarp();

    unsigned long long acc[6][2];
#pragma unroll
    for (int n = 0; n < 6; n++) { acc[n][0] = 0ull; acc[n][1] = 0ull; }

    const ulonglong2* wsU = reinterpret_cast<const ulonglong2*>(ws);

#pragma unroll 2
    for (int k4 = 0; k4 < 64; k4++) {
        float xf[6][4];
#pragma unroll
        for (int n = 0; n < 6; n++) {
            float4 q = reinterpret_cast<const float4*>(xw + n * 256)[k4]; // bcast
            xf[n][0] = q.x; xf[n][1] = q.y; xf[n][2] = q.z; xf[n][3] = q.w;
        }
#pragma unroll
        for (int kk = 0; kk < 4; kk++) {
            ulonglong2 w = wsU[(k4 * 4 + kk) * 32 + lane];
#pragma unroll
            for (int n = 0; n < 6; n++) {
                unsigned long long p = pack2(xf[n][kk]);
                fma2(acc[n][0], p, w.x);
                fma2(acc[n][1], p, w.y);
            }
        }
    }

    float4 b4  = __ldg(reinterpret_cast<const float4*>(fc_b) + lane);
    float4 g4  = __ldg(reinterpret_cast<const float4*>(ln_g) + lane);
    float4 bb4 = __ldg(reinterpret_cast<const float4*>(ln_b) + lane);

#pragma unroll
    for (int n = 0; n < 6; n++) {
        float y0, y1, y2, y3;
        unpack2(acc[n][0], y0, y1);
        unpack2(acc[n][1], y2, y3);
        float t = inrm[n];
        y0 = fmaf(t, b4.x, y0);
        y1 = fmaf(t, b4.y, y1);
        y2 = fmaf(t, b4.z, y2);
        y3 = fmaf(t, b4.w, y3);

        float s = y0 + y1 + y2 + y3;
#pragma unroll
        for (int o = 16; o > 0; o >>= 1) s += __shfl_xor_sync(0xffffffffu, s, o);
        float mu = s * (1.0f / 128.0f);

        float d0 = y0 - mu, d1 = y1 - mu, d2 = y2 - mu, d3 = y3 - mu;
        float ss = d0 * d0 + d1 * d1 + d2 * d2 + d3 * d3;
#pragma unroll
        for (int o = 16; o > 0; o >>= 1) ss += __shfl_xor_sync(0xffffffffu, ss, o);
        float rs = rsqrtf(ss * (1.0f / 128.0f) + LN_EPS);

        float4 o4;
        o4.x = fmaxf(fmaf(d0 * rs, g4.x, bb4.x), 0.f);
        o4.y = fmaxf(fmaf(d1 * rs, g4.y, bb4.y), 0.f);
        o4.z = fmaxf(fmaf(d2 * rs, g4.z, bb4.z), 0.f);
        o4.w = fmaxf(fmaf(d3 * rs, g4.w, bb4.w), 0.f);

        int v = v0 + n;
        if (v < nN)
            reinterpret_cast<float4*>(out)[(size_t)v * 32 + lane] = o4;
    }
}

// ---------------- launcher -----------------------------------------------------
extern "C" void kernel_launch(void* const* d_in, const int* in_sizes, int n_in,
                              void* d_out, int out_size) {
    const float* feat  = (const float*)d_in[0];
    const int*   src   = (const int*)d_in[1];
    const int*   dst   = (const int*)d_in[2];
    const float* fc_w  = (const float*)d_in[3];
    const float* fc_b  = (const float*)d_in[4];
    const float* res_w = (const float*)d_in[5];
    const float* ln_g  = (const float*)d_in[6];
    const float* ln_b  = (const float*)d_in[7];
    float* out = (float*)d_out;

    int nN = in_sizes[0] / DIM;   // 50000
    int nE = in_sizes[1];         // 600000

    // K0: zero agg + degree counters
    {
        int tot = nN * (DIM / 4);
        zero_kernel<<<(tot + 255) / 256, 256>>>(nN);
    }
    // K1: degrees
    degree_kernel<<<(nE + 255) / 256, 256>>>(src, dst, nE);
    // K2: scatter-add of normalized source features (warp per 2 edges)
    {
        long long warps = ((long long)nE + 1) / 2;
        long long threads = warps * 32;
        int blocks = (int)((threads + 255) / 256);
        scatter_kernel<<<blocks, 256>>>(feat, src, dst, nE);
    }
    // K3: fused GEMM + bias + in_norm scale + residual GEMM + LN + ReLU
    {
        const int SMEM = (32768 + 24576) * 4;  // 224 KB
        cudaFuncSetAttribute(final_kernel,
                             cudaFuncAttributeMaxDynamicSharedMemorySize, SMEM);
        int blocks = (nN + 95) / 96;
        final_kernel<<<blocks, 512, SMEM>>>(feat, fc_w, fc_b, res_w, ln_g, ln_b,
                                            out, nN);
    }
}